// round 13
// baseline (speedup 1.0000x reference)
#include <cuda_runtime.h>
#include <cuda_bf16.h>
#include <math_constants.h>
#include <cstdint>

// ---------------- problem constants ----------------
#define B_MOL 128
#define NA 48
#define NB 96
#define HID 200
#define AFD 39
#define BFD 50
#define LPROT 1000
#define C0 50
#define C1 96
#define C2 128
#define C3 200

// ---------------- device scratch ----------------
__device__ float g_bufA[B_MOL * 200 * LPROT];
__device__ float g_bufB[B_MOL * 200 * LPROT];
__device__ float g_emb[B_MOL * HID];
__device__ float g_prot[B_MOL * C3];
__device__ float g_wt[256 * 128 * 7];

// ---------------- cp.async helpers ----------------
__device__ __forceinline__ void cp_async4(void* dst_smem, const void* src, bool pred) {
    uint32_t d = (uint32_t)__cvta_generic_to_shared(dst_smem);
    int sz = pred ? 4 : 0;
    asm volatile("cp.async.ca.shared.global [%0], [%1], 4, %2;"
                 :: "r"(d), "l"(src), "r"(sz) : "memory");
}
__device__ __forceinline__ void cp_commit() {
    asm volatile("cp.async.commit_group;" ::: "memory");
}

// =====================================================================
// MPNN (R3 version — known good): one block/molecule, 512 threads.
// smem: binput | msg | tmp (each 96*200 f32) = 230400 B
// =====================================================================
__global__ __launch_bounds__(512)
void mpnn_kernel(const float* __restrict__ fatoms,
                 const float* __restrict__ fbonds,
                 const int*   __restrict__ agraph,
                 const int*   __restrict__ bgraph,
                 const float* __restrict__ W_i,
                 const float* __restrict__ W_h,
                 const float* __restrict__ W_o_w,
                 const float* __restrict__ W_o_b)
{
    extern __shared__ float sm[];
    float* binput = sm;               // 19200
    float* msg    = sm + 19200;       // 19200
    float* tmp    = sm + 38400;       // 19200

    const int b   = blockIdx.x;
    const int tid = threadIdx.x;
    const float* fb = fbonds + (size_t)b * NB * BFD;
    const float* fa = fatoms + (size_t)b * NA * AFD;
    const int*   bg = bgraph + (size_t)b * NB * 6;
    const int*   ag = agraph + (size_t)b * NA * 6;

    for (int idx = tid; idx < NB * BFD; idx += 512) tmp[idx] = fb[idx];
    __syncthreads();

    for (int task = tid; task < 24 * 50; task += 512) {
        const int i0 = (task / 50) * 4;
        const int h0 = (task % 50) * 4;
        float a[4][4];
        #pragma unroll
        for (int r = 0; r < 4; r++)
            #pragma unroll
            for (int c = 0; c < 4; c++) a[r][c] = 0.f;
        for (int k = 0; k < BFD; k++) {
            float4 w = *(const float4*)(W_i + k * HID + h0);
            #pragma unroll
            for (int r = 0; r < 4; r++) {
                float x = tmp[(i0 + r) * BFD + k];
                a[r][0] = fmaf(x, w.x, a[r][0]);
                a[r][1] = fmaf(x, w.y, a[r][1]);
                a[r][2] = fmaf(x, w.z, a[r][2]);
                a[r][3] = fmaf(x, w.w, a[r][3]);
            }
        }
        #pragma unroll
        for (int r = 0; r < 4; r++)
            #pragma unroll
            for (int c = 0; c < 4; c++) {
                binput[(i0 + r) * HID + h0 + c] = a[r][c];
                msg[(i0 + r) * HID + h0 + c]    = fmaxf(a[r][c], 0.f);
            }
    }
    __syncthreads();

    for (int d = 0; d < 2; d++) {
        for (int idx = tid; idx < NB * HID; idx += 512) {
            int i = idx / HID, h = idx - i * HID;
            float s = 0.f;
            #pragma unroll
            for (int j = 0; j < 6; j++) s += msg[bg[i * 6 + j] * HID + h];
            tmp[idx] = s;
        }
        __syncthreads();
        for (int task = tid; task < 24 * 50; task += 512) {
            const int i0 = (task / 50) * 4;
            const int h0 = (task % 50) * 4;
            float a[4][4];
            #pragma unroll
            for (int r = 0; r < 4; r++)
                #pragma unroll
                for (int c = 0; c < 4; c++) a[r][c] = binput[(i0 + r) * HID + h0 + c];
            for (int k = 0; k < HID; k++) {
                float4 w = *(const float4*)(W_h + k * HID + h0);
                #pragma unroll
                for (int r = 0; r < 4; r++) {
                    float x = tmp[(i0 + r) * HID + k];
                    a[r][0] = fmaf(x, w.x, a[r][0]);
                    a[r][1] = fmaf(x, w.y, a[r][1]);
                    a[r][2] = fmaf(x, w.z, a[r][2]);
                    a[r][3] = fmaf(x, w.w, a[r][3]);
                }
            }
            #pragma unroll
            for (int r = 0; r < 4; r++)
                #pragma unroll
                for (int c = 0; c < 4; c++)
                    msg[(i0 + r) * HID + h0 + c] = fmaxf(a[r][c], 0.f);
        }
        __syncthreads();
    }

    for (int idx = tid; idx < NA * HID; idx += 512) {
        int a = idx / HID, h = idx - a * HID;
        float s = 0.f;
        #pragma unroll
        for (int j = 0; j < 6; j++) s += msg[ag[a * 6 + j] * HID + h];
        tmp[idx] = s;
    }
    for (int idx = tid; idx < NA * AFD; idx += 512) tmp[NA * HID + idx] = fa[idx];
    __syncthreads();

    for (int task = tid; task < 12 * 50; task += 512) {
        const int a0i = (task / 50) * 4;
        const int h0  = (task % 50) * 4;
        float4 bb = *(const float4*)(W_o_b + h0);
        float a[4][4];
        #pragma unroll
        for (int r = 0; r < 4; r++) { a[r][0]=bb.x; a[r][1]=bb.y; a[r][2]=bb.z; a[r][3]=bb.w; }
        const float* fas = tmp + NA * HID;
        for (int k = 0; k < AFD; k++) {
            float4 w = *(const float4*)(W_o_w + k * HID + h0);
            #pragma unroll
            for (int r = 0; r < 4; r++) {
                float x = fas[(a0i + r) * AFD + k];
                a[r][0] = fmaf(x, w.x, a[r][0]);
                a[r][1] = fmaf(x, w.y, a[r][1]);
                a[r][2] = fmaf(x, w.z, a[r][2]);
                a[r][3] = fmaf(x, w.w, a[r][3]);
            }
        }
        for (int k = 0; k < HID; k++) {
            float4 w = *(const float4*)(W_o_w + (AFD + k) * HID + h0);
            #pragma unroll
            for (int r = 0; r < 4; r++) {
                float x = tmp[(a0i + r) * HID + k];
                a[r][0] = fmaf(x, w.x, a[r][0]);
                a[r][1] = fmaf(x, w.y, a[r][1]);
                a[r][2] = fmaf(x, w.z, a[r][2]);
                a[r][3] = fmaf(x, w.w, a[r][3]);
            }
        }
        #pragma unroll
        for (int r = 0; r < 4; r++)
            #pragma unroll
            for (int c = 0; c < 4; c++)
                binput[(a0i + r) * HID + h0 + c] = fmaxf(a[r][c], 0.f);
    }
    __syncthreads();

    for (int h = tid; h < HID; h += 512) {
        float s = 0.f;
        for (int a = 0; a < NA; a++) s += binput[a * HID + h];
        g_emb[b * HID + h] = s * (1.f / (float)NA);
    }
}

// =====================================================================
__global__ void embed_kernel(const int* __restrict__ seq,
                             const float* __restrict__ E)
{
    int idx = blockIdx.x * blockDim.x + threadIdx.x;
    const int total = B_MOL * C0 * LPROT;
    if (idx >= total) return;
    int l = idx % LPROT;
    int c = (idx / LPROT) % C0;
    int b = idx / (LPROT * C0);
    g_bufA[idx] = E[seq[b * LPROT + l] * C0 + c];
}

// =====================================================================
__global__ void wt_transpose_kernel(const float* __restrict__ w,
                                    float* __restrict__ wt,
                                    int Cin, int K, int Cout, int OCP)
{
    int idx = blockIdx.x * blockDim.x + threadIdx.x;
    int total = Cin * K * OCP;
    if (idx >= total) return;
    int oc  = idx % OCP;
    int row = idx / OCP;
    wt[idx] = (oc < Cout) ? w[(size_t)oc * Cin * K + row] : 0.f;
}

// =====================================================================
// conv implicit GEMM v7: R12 shape (32 oc x 256 pos, 4oc x 8pos/thread)
// + cp.async double-buffered staging (hide global-load latency).
// dyn smem: 2 x (16*264 input + 16K*32 weights) floats.
// =====================================================================
template <int K>
__global__ __launch_bounds__(256)
void conv_gemm_kernel(const float* __restrict__ in,
                      const float* __restrict__ wt,    // [Cin*K][OCP]
                      const float* __restrict__ bias,
                      float* __restrict__ out,
                      int Cin, int Cout, int OCP)
{
    extern __shared__ float smem[];
    constexpr int SIN = 16 * 264;
    constexpr int SW  = 16 * K * 32;
    float* s_in_base = smem;                 // [2][16][264]
    float* s_w_base  = smem + 2 * SIN;       // [2][16*K][32]
    constexpr int NQ = (8 + K - 1 + 3) / 4;

    const int b  = blockIdx.x;
    const int l0 = blockIdx.y * 256;
    const int o0 = blockIdx.z * 32;
    const int tid = threadIdx.x;
    const int ty = tid >> 5;      // 0..7  -> oc = o0 + ty*4 .. +3
    const int tx = tid & 31;      // 0..31 -> pos = l0 + tx*8 .. +7

    float acc[4][8];
    #pragma unroll
    for (int a = 0; a < 4; a++)
        #pragma unroll
        for (int r = 0; r < 8; r++) acc[a][r] = 0.f;

    const float* inb = in + (size_t)b * Cin * LPROT;
    const int nchunk = (Cin + 15) / 16;

    // ---- staging (cp.async, zero-fill via src-size 0) ----
    auto stage = [&](int c, int buf) {
        float* si = s_in_base + buf * SIN;
        float* sw = s_w_base  + buf * SW;
        for (int idx = tid; idx < SIN; idx += 256) {
            int ci = idx / 264, t = idx - ci * 264;
            int cig = c * 16 + ci;
            int gl = l0 + t - K / 2;
            bool ok = (cig < Cin && t < 256 + K - 1 && gl >= 0 && gl < LPROT);
            const float* src = ok ? (inb + (size_t)cig * LPROT + gl) : inb;
            cp_async4(si + idx, src, ok);
        }
        for (int idx = tid; idx < SW; idx += 256) {
            int row = idx >> 5, oc = idx & 31;
            int cig = c * 16 + row / K;
            bool ok = (cig < Cin);
            const float* src = ok ? (wt + (size_t)(cig * K + (row % K)) * OCP + o0 + oc) : wt;
            cp_async4(sw + idx, src, ok);
        }
        cp_commit();
    };

    stage(0, 0);

    for (int c = 0; c < nchunk; c++) {
        const int buf = c & 1;
        if (c + 1 < nchunk) {
            stage(c + 1, (c + 1) & 1);
            asm volatile("cp.async.wait_group 1;" ::: "memory");
        } else {
            asm volatile("cp.async.wait_group 0;" ::: "memory");
        }
        __syncthreads();

        const float* si = s_in_base + buf * SIN;
        const float* sw = s_w_base  + buf * SW;

        #pragma unroll 2
        for (int ci = 0; ci < 16; ci++) {
            float rin[NQ * 4];
            const float4* sp = (const float4*)(si + ci * 264 + tx * 8);
            #pragma unroll
            for (int q = 0; q < NQ; q++) {
                float4 v = sp[q];
                rin[q * 4 + 0] = v.x; rin[q * 4 + 1] = v.y;
                rin[q * 4 + 2] = v.z; rin[q * 4 + 3] = v.w;
            }
            #pragma unroll
            for (int k = 0; k < K; k++) {
                float4 w = *(const float4*)(sw + (ci * K + k) * 32 + ty * 4);
                #pragma unroll
                for (int r = 0; r < 8; r++) {
                    float x = rin[r + k];
                    acc[0][r] = fmaf(w.x, x, acc[0][r]);
                    acc[1][r] = fmaf(w.y, x, acc[1][r]);
                    acc[2][r] = fmaf(w.z, x, acc[2][r]);
                    acc[3][r] = fmaf(w.w, x, acc[3][r]);
                }
            }
        }
        __syncthreads();
    }

    const int lbase = l0 + tx * 8;
    #pragma unroll
    for (int a = 0; a < 4; a++) {
        int oc = o0 + ty * 4 + a;
        if (oc >= Cout) continue;
        float bv = bias[oc];
        float* op = out + ((size_t)b * Cout + oc) * LPROT + lbase;
        #pragma unroll
        for (int r = 0; r < 8; r++)
            if (lbase + r < LPROT) op[r] = fmaxf(acc[a][r] + bv, 0.f);
    }
}

// =====================================================================
__global__ void maxpool_kernel(const float* __restrict__ in, float* __restrict__ out)
{
    int gwarp = (blockIdx.x * blockDim.x + threadIdx.x) >> 5;
    int lane  = threadIdx.x & 31;
    const int rows = B_MOL * C3;
    if (gwarp >= rows) return;
    const float* p = in + (size_t)gwarp * LPROT;
    float m = -CUDART_INF_F;
    for (int l = lane; l < LPROT; l += 32) m = fmaxf(m, p[l]);
    #pragma unroll
    for (int s = 16; s; s >>= 1) m = fmaxf(m, __shfl_xor_sync(0xFFFFFFFFu, m, s));
    if (lane == 0) out[gwarp] = m;
}

// =====================================================================
__global__ void fc_kernel(const float* __restrict__ emb,
                          const float* __restrict__ prot,
                          const float* __restrict__ w0, const float* __restrict__ b0,
                          const float* __restrict__ w1, const float* __restrict__ b1,
                          const float* __restrict__ w2, const float* __restrict__ b2,
                          float* __restrict__ out)
{
    __shared__ float x[400];
    __shared__ float h1[200];
    __shared__ float h2[100];
    __shared__ float red[256];
    const int b = blockIdx.x;
    const int tid = threadIdx.x;

    for (int i = tid; i < 200; i += 256) {
        x[i]       = emb[b * 200 + i];
        x[200 + i] = prot[b * 200 + i];
    }
    __syncthreads();
    for (int j = tid; j < 200; j += 256) {
        float s = b0[j];
        for (int k = 0; k < 400; k++) s = fmaf(x[k], w0[k * 200 + j], s);
        h1[j] = fmaxf(s, 0.f);
    }
    __syncthreads();
    for (int j = tid; j < 100; j += 256) {
        float s = b1[j];
        for (int k = 0; k < 200; k++) s = fmaf(h1[k], w1[k * 100 + j], s);
        h2[j] = fmaxf(s, 0.f);
    }
    __syncthreads();
    float s = 0.f;
    for (int k = tid; k < 100; k += 256) s = fmaf(h2[k], w2[k], s);
    red[tid] = s;
    __syncthreads();
    for (int st = 128; st; st >>= 1) {
        if (tid < st) red[tid] += red[tid + st];
        __syncthreads();
    }
    if (tid == 0) out[b] = red[0] + b2[0];
}

// =====================================================================
extern "C" void kernel_launch(void* const* d_in, const int* in_sizes, int n_in,
                              void* d_out, int out_size)
{
    const float* fatoms  = (const float*)d_in[0];
    const float* fbonds  = (const float*)d_in[1];
    const int*   agraph  = (const int*)  d_in[2];
    const int*   bgraph  = (const int*)  d_in[3];
    const int*   seq     = (const int*)  d_in[4];
    const float* W_i     = (const float*)d_in[5];
    const float* W_h     = (const float*)d_in[6];
    const float* W_o_w   = (const float*)d_in[7];
    const float* W_o_b   = (const float*)d_in[8];
    const float* embedP  = (const float*)d_in[9];
    const float* c0w     = (const float*)d_in[10];
    const float* c0b     = (const float*)d_in[11];
    const float* c1w     = (const float*)d_in[12];
    const float* c1b     = (const float*)d_in[13];
    const float* c2w     = (const float*)d_in[14];
    const float* c2b     = (const float*)d_in[15];
    const float* fc0w    = (const float*)d_in[16];
    const float* fc0b    = (const float*)d_in[17];
    const float* fc1w    = (const float*)d_in[18];
    const float* fc1b    = (const float*)d_in[19];
    const float* fc2w    = (const float*)d_in[20];
    const float* fc2b    = (const float*)d_in[21];
    float* out = (float*)d_out;

    float *bufA, *bufB, *emb, *prot, *wt;
    cudaGetSymbolAddress((void**)&bufA, g_bufA);
    cudaGetSymbolAddress((void**)&bufB, g_bufB);
    cudaGetSymbolAddress((void**)&emb,  g_emb);
    cudaGetSymbolAddress((void**)&prot, g_prot);
    cudaGetSymbolAddress((void**)&wt,   g_wt);

    const int mpnn_smem = 3 * NB * HID * sizeof(float);   // 230400 B
    cudaFuncSetAttribute(mpnn_kernel, cudaFuncAttributeMaxDynamicSharedMemorySize, mpnn_smem);

    const int smem3 = (2 * 16 * 264 + 2 * 16 * 3 * 32) * sizeof(float);
    const int smem5 = (2 * 16 * 264 + 2 * 16 * 5 * 32) * sizeof(float);
    const int smem7 = (2 * 16 * 264 + 2 * 16 * 7 * 32) * sizeof(float);
    cudaFuncSetAttribute(conv_gemm_kernel<3>, cudaFuncAttributeMaxDynamicSharedMemorySize, smem3);
    cudaFuncSetAttribute(conv_gemm_kernel<5>, cudaFuncAttributeMaxDynamicSharedMemorySize, smem5);
    cudaFuncSetAttribute(conv_gemm_kernel<7>, cudaFuncAttributeMaxDynamicSharedMemorySize, smem7);

    // 1. MPNN -> g_emb
    mpnn_kernel<<<B_MOL, 512, mpnn_smem>>>(fatoms, fbonds, agraph, bgraph,
                                           W_i, W_h, W_o_w, W_o_b);

    // 2. protein embedding -> bufA
    {
        int total = B_MOL * C0 * LPROT;
        embed_kernel<<<(total + 255) / 256, 256>>>(seq, embedP);
    }

    // 3. conv tower (32-oc tiles, double-buffered cp.async staging)
    {   // conv0: 50 -> 96, K=3, z = 3
        int total = C0 * 3 * 128;
        wt_transpose_kernel<<<(total + 255) / 256, 256>>>(c0w, wt, C0, 3, C1, 128);
        dim3 g(B_MOL, 4, 3);
        conv_gemm_kernel<3><<<g, 256, smem3>>>(bufA, wt, c0b, bufB, C0, C1, 128);
    }
    {   // conv1: 96 -> 128, K=5, z = 4
        int total = C1 * 5 * 128;
        wt_transpose_kernel<<<(total + 255) / 256, 256>>>(c1w, wt, C1, 5, C2, 128);
        dim3 g(B_MOL, 4, 4);
        conv_gemm_kernel<5><<<g, 256, smem5>>>(bufB, wt, c1b, bufA, C1, C2, 128);
    }
    {   // conv2: 128 -> 200, K=7, z = 7 (224 covered, 11% pad)
        int total = C2 * 7 * 256;
        wt_transpose_kernel<<<(total + 255) / 256, 256>>>(c2w, wt, C2, 7, C3, 256);
        dim3 g(B_MOL, 4, 7);
        conv_gemm_kernel<7><<<g, 256, smem7>>>(bufA, wt, c2b, bufB, C2, C3, 256);
    }

    // 4. adaptive max pool -> g_prot
    {
        int rows = B_MOL * C3;
        int blocks = (rows + 7) / 8;
        maxpool_kernel<<<blocks, 256>>>(bufB, prot);
    }

    // 5. FC head -> out
    fc_kernel<<<B_MOL, 256>>>(emb, prot, fc0w, fc0b, fc1w, fc1b, fc2w, fc2b, out);
}

// round 15
// speedup vs baseline: 1.2495x; 1.2495x over previous
#include <cuda_runtime.h>
#include <cuda_bf16.h>
#include <math_constants.h>
#include <cstdint>

// ---------------- problem constants ----------------
#define B_MOL 128
#define NA 48
#define NB 96
#define HID 200
#define AFD 39
#define BFD 50
#define LPROT 1000
#define C0 50
#define C1 96
#define C2 128
#define C3 200

// ---------------- device scratch ----------------
__device__ float g_bufA[B_MOL * 200 * LPROT];
__device__ float g_bufB[B_MOL * 200 * LPROT];
__device__ float g_emb[B_MOL * HID];
__device__ float g_prot[B_MOL * C3];
// packed input: [b][l][chunk][48] bf16, max nchunk = 8
__device__ __nv_bfloat16 g_inpack[(size_t)B_MOL * LPROT * 8 * 48];
// prepacked weights: [tile][chunk][ktap][oc128][48] bf16 (max 2*8*7*128*48)
__device__ __nv_bfloat16 g_wtp[(size_t)2 * 8 * 7 * 128 * 48];

// ---------------- bf16 HMMA helper (sm_80+ PTX, compiles for compute_103) --
__device__ __forceinline__ void mma16816(float& d0, float& d1, float& d2, float& d3,
                                         uint32_t a0, uint32_t a1, uint32_t a2, uint32_t a3,
                                         uint32_t b0, uint32_t b1) {
    asm volatile(
        "mma.sync.aligned.m16n8k16.row.col.f32.bf16.bf16.f32 "
        "{%0,%1,%2,%3}, {%4,%5,%6,%7}, {%8,%9}, {%0,%1,%2,%3};"
        : "+f"(d0), "+f"(d1), "+f"(d2), "+f"(d3)
        : "r"(a0), "r"(a1), "r"(a2), "r"(a3), "r"(b0), "r"(b1));
}

// =====================================================================
// MPNN (R3 — known good): one block/molecule, 512 threads, 230400B smem
// =====================================================================
__global__ __launch_bounds__(512)
void mpnn_kernel(const float* __restrict__ fatoms,
                 const float* __restrict__ fbonds,
                 const int*   __restrict__ agraph,
                 const int*   __restrict__ bgraph,
                 const float* __restrict__ W_i,
                 const float* __restrict__ W_h,
                 const float* __restrict__ W_o_w,
                 const float* __restrict__ W_o_b)
{
    extern __shared__ float sm[];
    float* binput = sm;
    float* msg    = sm + 19200;
    float* tmp    = sm + 38400;

    const int b   = blockIdx.x;
    const int tid = threadIdx.x;
    const float* fb = fbonds + (size_t)b * NB * BFD;
    const float* fa = fatoms + (size_t)b * NA * AFD;
    const int*   bg = bgraph + (size_t)b * NB * 6;
    const int*   ag = agraph + (size_t)b * NA * 6;

    for (int idx = tid; idx < NB * BFD; idx += 512) tmp[idx] = fb[idx];
    __syncthreads();

    for (int task = tid; task < 24 * 50; task += 512) {
        const int i0 = (task / 50) * 4;
        const int h0 = (task % 50) * 4;
        float a[4][4];
        #pragma unroll
        for (int r = 0; r < 4; r++)
            #pragma unroll
            for (int c = 0; c < 4; c++) a[r][c] = 0.f;
        for (int k = 0; k < BFD; k++) {
            float4 w = *(const float4*)(W_i + k * HID + h0);
            #pragma unroll
            for (int r = 0; r < 4; r++) {
                float x = tmp[(i0 + r) * BFD + k];
                a[r][0] = fmaf(x, w.x, a[r][0]);
                a[r][1] = fmaf(x, w.y, a[r][1]);
                a[r][2] = fmaf(x, w.z, a[r][2]);
                a[r][3] = fmaf(x, w.w, a[r][3]);
            }
        }
        #pragma unroll
        for (int r = 0; r < 4; r++)
            #pragma unroll
            for (int c = 0; c < 4; c++) {
                binput[(i0 + r) * HID + h0 + c] = a[r][c];
                msg[(i0 + r) * HID + h0 + c]    = fmaxf(a[r][c], 0.f);
            }
    }
    __syncthreads();

    for (int d = 0; d < 2; d++) {
        for (int idx = tid; idx < NB * HID; idx += 512) {
            int i = idx / HID, h = idx - i * HID;
            float s = 0.f;
            #pragma unroll
            for (int j = 0; j < 6; j++) s += msg[bg[i * 6 + j] * HID + h];
            tmp[idx] = s;
        }
        __syncthreads();
        for (int task = tid; task < 24 * 50; task += 512) {
            const int i0 = (task / 50) * 4;
            const int h0 = (task % 50) * 4;
            float a[4][4];
            #pragma unroll
            for (int r = 0; r < 4; r++)
                #pragma unroll
                for (int c = 0; c < 4; c++) a[r][c] = binput[(i0 + r) * HID + h0 + c];
            for (int k = 0; k < HID; k++) {
                float4 w = *(const float4*)(W_h + k * HID + h0);
                #pragma unroll
                for (int r = 0; r < 4; r++) {
                    float x = tmp[(i0 + r) * HID + k];
                    a[r][0] = fmaf(x, w.x, a[r][0]);
                    a[r][1] = fmaf(x, w.y, a[r][1]);
                    a[r][2] = fmaf(x, w.z, a[r][2]);
                    a[r][3] = fmaf(x, w.w, a[r][3]);
                }
            }
            #pragma unroll
            for (int r = 0; r < 4; r++)
                #pragma unroll
                for (int c = 0; c < 4; c++)
                    msg[(i0 + r) * HID + h0 + c] = fmaxf(a[r][c], 0.f);
        }
        __syncthreads();
    }

    for (int idx = tid; idx < NA * HID; idx += 512) {
        int a = idx / HID, h = idx - a * HID;
        float s = 0.f;
        #pragma unroll
        for (int j = 0; j < 6; j++) s += msg[ag[a * 6 + j] * HID + h];
        tmp[idx] = s;
    }
    for (int idx = tid; idx < NA * AFD; idx += 512) tmp[NA * HID + idx] = fa[idx];
    __syncthreads();

    for (int task = tid; task < 12 * 50; task += 512) {
        const int a0i = (task / 50) * 4;
        const int h0  = (task % 50) * 4;
        float4 bb = *(const float4*)(W_o_b + h0);
        float a[4][4];
        #pragma unroll
        for (int r = 0; r < 4; r++) { a[r][0]=bb.x; a[r][1]=bb.y; a[r][2]=bb.z; a[r][3]=bb.w; }
        const float* fas = tmp + NA * HID;
        for (int k = 0; k < AFD; k++) {
            float4 w = *(const float4*)(W_o_w + k * HID + h0);
            #pragma unroll
            for (int r = 0; r < 4; r++) {
                float x = fas[(a0i + r) * AFD + k];
                a[r][0] = fmaf(x, w.x, a[r][0]);
                a[r][1] = fmaf(x, w.y, a[r][1]);
                a[r][2] = fmaf(x, w.z, a[r][2]);
                a[r][3] = fmaf(x, w.w, a[r][3]);
            }
        }
        for (int k = 0; k < HID; k++) {
            float4 w = *(const float4*)(W_o_w + (AFD + k) * HID + h0);
            #pragma unroll
            for (int r = 0; r < 4; r++) {
                float x = tmp[(a0i + r) * HID + k];
                a[r][0] = fmaf(x, w.x, a[r][0]);
                a[r][1] = fmaf(x, w.y, a[r][1]);
                a[r][2] = fmaf(x, w.z, a[r][2]);
                a[r][3] = fmaf(x, w.w, a[r][3]);
            }
        }
        #pragma unroll
        for (int r = 0; r < 4; r++)
            #pragma unroll
            for (int c = 0; c < 4; c++)
                binput[(a0i + r) * HID + h0 + c] = fmaxf(a[r][c], 0.f);
    }
    __syncthreads();

    for (int h = tid; h < HID; h += 512) {
        float s = 0.f;
        for (int a = 0; a < NA; a++) s += binput[a * HID + h];
        g_emb[b * HID + h] = s * (1.f / (float)NA);
    }
}

// =====================================================================
__global__ void embed_kernel(const int* __restrict__ seq,
                             const float* __restrict__ E)
{
    int idx = blockIdx.x * blockDim.x + threadIdx.x;
    const int total = B_MOL * C0 * LPROT;
    if (idx >= total) return;
    int l = idx % LPROT;
    int c = (idx / LPROT) % C0;
    int b = idx / (LPROT * C0);
    g_bufA[idx] = E[seq[b * LPROT + l] * C0 + c];
}

// =====================================================================
// weight prepack: w[Cout][Cin][K] fp32 -> [tile][chunk][ktap][oc128][48] bf16
// 48-slot split layout along K: [0..15]=Whi [16..31]=Whi [32..47]=Wlo
// =====================================================================
__global__ void wt_prepack_kernel(const float* __restrict__ w,
                                  int Cout, int Cin, int K,
                                  int nchunk, int ntiles)
{
    int idx = blockIdx.x * blockDim.x + threadIdx.x;
    int total = ntiles * nchunk * K * 128 * 48;
    if (idx >= total) return;
    int u48 = idx % 48;
    int oc  = (idx / 48) % 128;
    int kt  = (idx / (48 * 128)) % K;
    int c   = (idx / (48 * 128 * K)) % nchunk;
    int t   =  idx / (48 * 128 * K * nchunk);

    int part = u48 >> 4;       // 0,1 = hi ; 2 = lo
    int cii  = u48 & 15;
    int ci   = c * 16 + cii;
    int ocg  = t * 128 + oc;

    __nv_bfloat16 val = __float2bfloat16(0.f);
    if (ocg < Cout && ci < Cin) {
        float x = w[((size_t)ocg * Cin + ci) * K + kt];
        __nv_bfloat16 hi = __float2bfloat16(x);
        val = (part < 2) ? hi : __float2bfloat16(x - __bfloat162float(hi));
    }
    g_wtp[idx] = val;
}

// =====================================================================
// input prepack: in[b][ci][l] fp32 -> g_inpack[b][l][chunk][48] bf16
// slots: [0..15]=hi, [16..31]=lo, [32..47]=hi
// =====================================================================
__global__ void in_prepack_kernel(const float* __restrict__ in,
                                  int Cin, int nchunk)
{
    int idx = blockIdx.x * blockDim.x + threadIdx.x;
    int total = B_MOL * nchunk * LPROT;
    if (idx >= total) return;
    int l = idx % LPROT;
    int c = (idx / LPROT) % nchunk;
    int b = idx / (LPROT * nchunk);

    unsigned short s[48];
    #pragma unroll
    for (int cii = 0; cii < 16; cii++) {
        int ci = c * 16 + cii;
        float x = (ci < Cin) ? in[((size_t)b * Cin + ci) * LPROT + l] : 0.f;
        __nv_bfloat16 hi = __float2bfloat16(x);
        __nv_bfloat16 lo = __float2bfloat16(x - __bfloat162float(hi));
        unsigned short hb = __bfloat16_as_ushort(hi);
        s[cii]      = hb;
        s[16 + cii] = __bfloat16_as_ushort(lo);
        s[32 + cii] = hb;
    }
    uint4* dst = (uint4*)(g_inpack + ((size_t)(b * LPROT + l) * nchunk + c) * 48);
    const uint4* sv = (const uint4*)s;
    #pragma unroll
    for (int q = 0; q < 6; q++) dst[q] = sv[q];
}

// =====================================================================
// conv via warp HMMA (m16n8k16 bf16): block = 128 oc x 128 pos, 8 warps.
// Warp grid 2(m) x 4(n); warp tile 64 oc x 32 pos.
// smem: s_a[K][128][52] bf16 (per-chunk weights), s_b[128+K-1][52] bf16.
// B rows shifted by ktap (p0 + kt) to realize the conv.
// =====================================================================
template <int K, int NCHUNK>
__global__ __launch_bounds__(256)
void conv_mma_kernel(const float* __restrict__ bias,
                     float* __restrict__ out, int Cout)
{
    constexpr int PW = 128 + K - 1;
    constexpr int AROWS = K * 128;
    extern __shared__ __nv_bfloat16 smem[];
    __nv_bfloat16* s_a = smem;                  // [K*128][52]
    __nv_bfloat16* s_b = smem + AROWS * 52;     // [PW][52]

    const int tid  = threadIdx.x;
    const int lane = tid & 31;
    const int wid  = tid >> 5;
    const int wm   = wid & 1;        // 0,1  -> oc 64*wm
    const int wn   = wid >> 1;       // 0..3 -> pos 32*wn
    const int b    = blockIdx.x;
    const int l0   = blockIdx.y * 128;
    const int oc0  = blockIdx.z * 128;
    const int gid  = lane >> 2;      // groupID
    const int qid  = lane & 3;       // thread in group

    const __nv_bfloat16* wp_tile =
        g_wtp + (size_t)blockIdx.z * NCHUNK * AROWS * 48;

    float acc[4][4][4];
    #pragma unroll
    for (int mi = 0; mi < 4; mi++)
        #pragma unroll
        for (int ni = 0; ni < 4; ni++)
            #pragma unroll
            for (int q = 0; q < 4; q++) acc[mi][ni][q] = 0.f;

    for (int c = 0; c < NCHUNK; c++) {
        // stage A: AROWS rows x 48 elems (12 uint2 per row), dst stride 52
        for (int idx = tid; idx < AROWS * 12; idx += 256) {
            int row = idx / 12, u = idx - row * 12;
            uint2 v = *(const uint2*)(wp_tile + ((size_t)c * AROWS + row) * 48 + u * 4);
            *(uint2*)(s_a + row * 52 + u * 4) = v;
        }
        // stage B: PW rows
        for (int idx = tid; idx < PW * 12; idx += 256) {
            int p = idx / 12, u = idx - p * 12;
            int l = l0 + p - K / 2;
            uint2 v = make_uint2(0u, 0u);
            if (l >= 0 && l < LPROT)
                v = *(const uint2*)(g_inpack + ((size_t)(b * LPROT + l) * NCHUNK + c) * 48 + u * 4);
            *(uint2*)(s_b + p * 52 + u * 4) = v;
        }
        __syncthreads();

        #pragma unroll 1
        for (int kt = 0; kt < K; kt++) {
            const __nv_bfloat16* sa = s_a + kt * 128 * 52;
            #pragma unroll
            for (int s = 0; s < 3; s++) {
                const int k0 = s * 16 + qid * 2;
                uint32_t afr[4][4];
                #pragma unroll
                for (int mi = 0; mi < 4; mi++) {
                    int r0 = wm * 64 + mi * 16 + gid;
                    afr[mi][0] = *(const uint32_t*)(sa + (r0)     * 52 + k0);
                    afr[mi][1] = *(const uint32_t*)(sa + (r0 + 8) * 52 + k0);
                    afr[mi][2] = *(const uint32_t*)(sa + (r0)     * 52 + k0 + 8);
                    afr[mi][3] = *(const uint32_t*)(sa + (r0 + 8) * 52 + k0 + 8);
                }
                uint32_t bfr[4][2];
                #pragma unroll
                for (int ni = 0; ni < 4; ni++) {
                    int p0 = wn * 32 + ni * 8 + gid + kt;
                    bfr[ni][0] = *(const uint32_t*)(s_b + p0 * 52 + k0);
                    bfr[ni][1] = *(const uint32_t*)(s_b + p0 * 52 + k0 + 8);
                }
                #pragma unroll
                for (int mi = 0; mi < 4; mi++)
                    #pragma unroll
                    for (int ni = 0; ni < 4; ni++)
                        mma16816(acc[mi][ni][0], acc[mi][ni][1], acc[mi][ni][2], acc[mi][ni][3],
                                 afr[mi][0], afr[mi][1], afr[mi][2], afr[mi][3],
                                 bfr[ni][0], bfr[ni][1]);
            }
        }
        __syncthreads();
    }

    // epilogue: c0=(r,col) c1=(r,col+1) c2=(r+8,col) c3=(r+8,col+1)
    #pragma unroll
    for (int mi = 0; mi < 4; mi++) {
        int oc = oc0 + wm * 64 + mi * 16 + gid;
        #pragma unroll
        for (int ni = 0; ni < 4; ni++) {
            int col = l0 + wn * 32 + ni * 8 + qid * 2;
            if (col < LPROT) {
                if (oc < Cout) {
                    float bv = bias[oc];
                    float2 v;
                    v.x = fmaxf(acc[mi][ni][0] + bv, 0.f);
                    v.y = fmaxf(acc[mi][ni][1] + bv, 0.f);
                    *(float2*)(out + ((size_t)b * Cout + oc) * LPROT + col) = v;
                }
                if (oc + 8 < Cout) {
                    float bv = bias[oc + 8];
                    float2 v;
                    v.x = fmaxf(acc[mi][ni][2] + bv, 0.f);
                    v.y = fmaxf(acc[mi][ni][3] + bv, 0.f);
                    *(float2*)(out + ((size_t)b * Cout + oc + 8) * LPROT + col) = v;
                }
            }
        }
    }
}

// =====================================================================
__global__ void maxpool_kernel(const float* __restrict__ in, float* __restrict__ out)
{
    int gwarp = (blockIdx.x * blockDim.x + threadIdx.x) >> 5;
    int lane  = threadIdx.x & 31;
    const int rows = B_MOL * C3;
    if (gwarp >= rows) return;
    const float* p = in + (size_t)gwarp * LPROT;
    float m = -CUDART_INF_F;
    for (int l = lane; l < LPROT; l += 32) m = fmaxf(m, p[l]);
    #pragma unroll
    for (int s = 16; s; s >>= 1) m = fmaxf(m, __shfl_xor_sync(0xFFFFFFFFu, m, s));
    if (lane == 0) out[gwarp] = m;
}

// =====================================================================
__global__ void fc_kernel(const float* __restrict__ emb,
                          const float* __restrict__ prot,
                          const float* __restrict__ w0, const float* __restrict__ b0,
                          const float* __restrict__ w1, const float* __restrict__ b1,
                          const float* __restrict__ w2, const float* __restrict__ b2,
                          float* __restrict__ out)
{
    __shared__ float x[400];
    __shared__ float h1[200];
    __shared__ float h2[100];
    __shared__ float red[256];
    const int b = blockIdx.x;
    const int tid = threadIdx.x;

    for (int i = tid; i < 200; i += 256) {
        x[i]       = emb[b * 200 + i];
        x[200 + i] = prot[b * 200 + i];
    }
    __syncthreads();
    for (int j = tid; j < 200; j += 256) {
        float s = b0[j];
        for (int k = 0; k < 400; k++) s = fmaf(x[k], w0[k * 200 + j], s);
        h1[j] = fmaxf(s, 0.f);
    }
    __syncthreads();
    for (int j = tid; j < 100; j += 256) {
        float s = b1[j];
        for (int k = 0; k < 200; k++) s = fmaf(h1[k], w1[k * 100 + j], s);
        h2[j] = fmaxf(s, 0.f);
    }
    __syncthreads();
    float s = 0.f;
    for (int k = tid; k < 100; k += 256) s = fmaf(h2[k], w2[k], s);
    red[tid] = s;
    __syncthreads();
    for (int st = 128; st; st >>= 1) {
        if (tid < st) red[tid] += red[tid + st];
        __syncthreads();
    }
    if (tid == 0) out[b] = red[0] + b2[0];
}

// =====================================================================
extern "C" void kernel_launch(void* const* d_in, const int* in_sizes, int n_in,
                              void* d_out, int out_size)
{
    const float* fatoms  = (const float*)d_in[0];
    const float* fbonds  = (const float*)d_in[1];
    const int*   agraph  = (const int*)  d_in[2];
    const int*   bgraph  = (const int*)  d_in[3];
    const int*   seq     = (const int*)  d_in[4];
    const float* W_i     = (const float*)d_in[5];
    const float* W_h     = (const float*)d_in[6];
    const float* W_o_w   = (const float*)d_in[7];
    const float* W_o_b   = (const float*)d_in[8];
    const float* embedP  = (const float*)d_in[9];
    const float* c0w     = (const float*)d_in[10];
    const float* c0b     = (const float*)d_in[11];
    const float* c1w     = (const float*)d_in[12];
    const float* c1b     = (const float*)d_in[13];
    const float* c2w     = (const float*)d_in[14];
    const float* c2b     = (const float*)d_in[15];
    const float* fc0w    = (const float*)d_in[16];
    const float* fc0b    = (const float*)d_in[17];
    const float* fc1w    = (const float*)d_in[18];
    const float* fc1b    = (const float*)d_in[19];
    const float* fc2w    = (const float*)d_in[20];
    const float* fc2b    = (const float*)d_in[21];
    float* out = (float*)d_out;

    float *bufA, *bufB, *emb, *prot;
    cudaGetSymbolAddress((void**)&bufA, g_bufA);
    cudaGetSymbolAddress((void**)&bufB, g_bufB);
    cudaGetSymbolAddress((void**)&emb,  g_emb);
    cudaGetSymbolAddress((void**)&prot, g_prot);

    const int mpnn_smem = 3 * NB * HID * sizeof(float);   // 230400 B
    cudaFuncSetAttribute(mpnn_kernel, cudaFuncAttributeMaxDynamicSharedMemorySize, mpnn_smem);

    // conv smem: (K*128*52 + (128+K-1)*52) bf16 elems
    const int smem0 = (3 * 128 * 52 + 130 * 52) * 2;   //  53,456 B
    const int smem1 = (5 * 128 * 52 + 132 * 52) * 2;   //  80,288 B
    const int smem2 = (7 * 128 * 52 + 134 * 52) * 2;   // 107,120 B
    cudaFuncSetAttribute((conv_mma_kernel<3, 4>), cudaFuncAttributeMaxDynamicSharedMemorySize, smem0);
    cudaFuncSetAttribute((conv_mma_kernel<5, 6>), cudaFuncAttributeMaxDynamicSharedMemorySize, smem1);
    cudaFuncSetAttribute((conv_mma_kernel<7, 8>), cudaFuncAttributeMaxDynamicSharedMemorySize, smem2);

    // 1. MPNN -> g_emb
    mpnn_kernel<<<B_MOL, 512, mpnn_smem>>>(fatoms, fbonds, agraph, bgraph,
                                           W_i, W_h, W_o_w, W_o_b);

    // 2. protein embedding -> bufA (fp32 [b][50][l])
    {
        int total = B_MOL * C0 * LPROT;
        embed_kernel<<<(total + 255) / 256, 256>>>(seq, embedP);
    }

    // 3. conv tower via HMMA (split-bf16)
    {   // conv0: 50 -> 96, K=3, nchunk=4, 1 oc-tile
        int wtot = 1 * 4 * 3 * 128 * 48;
        wt_prepack_kernel<<<(wtot + 255) / 256, 256>>>(c0w, C1, C0, 3, 4, 1);
        int itot = B_MOL * 4 * LPROT;
        in_prepack_kernel<<<(itot + 255) / 256, 256>>>(bufA, C0, 4);
        dim3 g(B_MOL, 8, 1);
        conv_mma_kernel<3, 4><<<g, 256, smem0>>>(c0b, bufB, C1);
    }
    {   // conv1: 96 -> 128, K=5, nchunk=6, 1 oc-tile
        int wtot = 1 * 6 * 5 * 128 * 48;
        wt_prepack_kernel<<<(wtot + 255) / 256, 256>>>(c1w, C2, C1, 5, 6, 1);
        int itot = B_MOL * 6 * LPROT;
        in_prepack_kernel<<<(itot + 255) / 256, 256>>>(bufB, C1, 6);
        dim3 g(B_MOL, 8, 1);
        conv_mma_kernel<5, 6><<<g, 256, smem1>>>(c1b, bufA, C2);
    }
    {   // conv2: 128 -> 200, K=7, nchunk=8, 2 oc-tiles
        int wtot = 2 * 8 * 7 * 128 * 48;
        wt_prepack_kernel<<<(wtot + 255) / 256, 256>>>(c2w, C3, C2, 7, 8, 2);
        int itot = B_MOL * 8 * LPROT;
        in_prepack_kernel<<<(itot + 255) / 256, 256>>>(bufA, C2, 8);
        dim3 g(B_MOL, 8, 2);
        conv_mma_kernel<7, 8><<<g, 256, smem2>>>(c2b, bufB, C3);
    }

    // 4. adaptive max pool -> g_prot
    {
        int rows = B_MOL * C3;
        int blocks = (rows + 7) / 8;
        maxpool_kernel<<<blocks, 256>>>(bufB, prot);
    }

    // 5. FC head -> out
    fc_kernel<<<B_MOL, 256>>>(emb, prot, fc0w, fc0b, fc1w, fc1b, fc2w, fc2b, out);
}

// round 16
// speedup vs baseline: 1.3031x; 1.0429x over previous
#include <cuda_runtime.h>
#include <cuda_bf16.h>
#include <math_constants.h>
#include <cstdint>

// ---------------- problem constants ----------------
#define B_MOL 128
#define NA 48
#define NB 96
#define HID 200
#define AFD 39
#define BFD 50
#define LPROT 1000
#define C0 50
#define C1 96
#define C2 128
#define C3 200

// ---------------- device scratch ----------------
__device__ float g_bufA[B_MOL * 200 * LPROT];
__device__ float g_bufB[B_MOL * 200 * LPROT];
__device__ float g_emb[B_MOL * HID];
__device__ float g_prot[B_MOL * C3];
// packed input: [b][l][chunk][48] bf16, max nchunk = 8
__device__ __nv_bfloat16 g_inpack[(size_t)B_MOL * LPROT * 8 * 48];
// prepacked weights, one region per layer:
//   L0: 1*4*3*128*48 = 73728 ; L1: 1*6*5*128*48 = 184320 ; L2: 2*8*7*128*48 = 688128
#define WT0_OFF 0
#define WT1_OFF 73728
#define WT2_OFF (73728 + 184320)
__device__ __nv_bfloat16 g_wtp[73728 + 184320 + 688128];

// ---------------- bf16 HMMA helper (sm_80+ PTX) ----------------
__device__ __forceinline__ void mma16816(float& d0, float& d1, float& d2, float& d3,
                                         uint32_t a0, uint32_t a1, uint32_t a2, uint32_t a3,
                                         uint32_t b0, uint32_t b1) {
    asm volatile(
        "mma.sync.aligned.m16n8k16.row.col.f32.bf16.bf16.f32 "
        "{%0,%1,%2,%3}, {%4,%5,%6,%7}, {%8,%9}, {%0,%1,%2,%3};"
        : "+f"(d0), "+f"(d1), "+f"(d2), "+f"(d3)
        : "r"(a0), "r"(a1), "r"(a2), "r"(a3), "r"(b0), "r"(b1));
}

// =====================================================================
// MPNN (R3 — known good): one block/molecule, 512 threads, 230400B smem
// =====================================================================
__global__ __launch_bounds__(512)
void mpnn_kernel(const float* __restrict__ fatoms,
                 const float* __restrict__ fbonds,
                 const int*   __restrict__ agraph,
                 const int*   __restrict__ bgraph,
                 const float* __restrict__ W_i,
                 const float* __restrict__ W_h,
                 const float* __restrict__ W_o_w,
                 const float* __restrict__ W_o_b)
{
    extern __shared__ float sm[];
    float* binput = sm;
    float* msg    = sm + 19200;
    float* tmp    = sm + 38400;

    const int b   = blockIdx.x;
    const int tid = threadIdx.x;
    const float* fb = fbonds + (size_t)b * NB * BFD;
    const float* fa = fatoms + (size_t)b * NA * AFD;
    const int*   bg = bgraph + (size_t)b * NB * 6;
    const int*   ag = agraph + (size_t)b * NA * 6;

    for (int idx = tid; idx < NB * BFD; idx += 512) tmp[idx] = fb[idx];
    __syncthreads();

    for (int task = tid; task < 24 * 50; task += 512) {
        const int i0 = (task / 50) * 4;
        const int h0 = (task % 50) * 4;
        float a[4][4];
        #pragma unroll
        for (int r = 0; r < 4; r++)
            #pragma unroll
            for (int c = 0; c < 4; c++) a[r][c] = 0.f;
        for (int k = 0; k < BFD; k++) {
            float4 w = *(const float4*)(W_i + k * HID + h0);
            #pragma unroll
            for (int r = 0; r < 4; r++) {
                float x = tmp[(i0 + r) * BFD + k];
                a[r][0] = fmaf(x, w.x, a[r][0]);
                a[r][1] = fmaf(x, w.y, a[r][1]);
                a[r][2] = fmaf(x, w.z, a[r][2]);
                a[r][3] = fmaf(x, w.w, a[r][3]);
            }
        }
        #pragma unroll
        for (int r = 0; r < 4; r++)
            #pragma unroll
            for (int c = 0; c < 4; c++) {
                binput[(i0 + r) * HID + h0 + c] = a[r][c];
                msg[(i0 + r) * HID + h0 + c]    = fmaxf(a[r][c], 0.f);
            }
    }
    __syncthreads();

    for (int d = 0; d < 2; d++) {
        for (int idx = tid; idx < NB * HID; idx += 512) {
            int i = idx / HID, h = idx - i * HID;
            float s = 0.f;
            #pragma unroll
            for (int j = 0; j < 6; j++) s += msg[bg[i * 6 + j] * HID + h];
            tmp[idx] = s;
        }
        __syncthreads();
        for (int task = tid; task < 24 * 50; task += 512) {
            const int i0 = (task / 50) * 4;
            const int h0 = (task % 50) * 4;
            float a[4][4];
            #pragma unroll
            for (int r = 0; r < 4; r++)
                #pragma unroll
                for (int c = 0; c < 4; c++) a[r][c] = binput[(i0 + r) * HID + h0 + c];
            for (int k = 0; k < HID; k++) {
                float4 w = *(const float4*)(W_h + k * HID + h0);
                #pragma unroll
                for (int r = 0; r < 4; r++) {
                    float x = tmp[(i0 + r) * HID + k];
                    a[r][0] = fmaf(x, w.x, a[r][0]);
                    a[r][1] = fmaf(x, w.y, a[r][1]);
                    a[r][2] = fmaf(x, w.z, a[r][2]);
                    a[r][3] = fmaf(x, w.w, a[r][3]);
                }
            }
            #pragma unroll
            for (int r = 0; r < 4; r++)
                #pragma unroll
                for (int c = 0; c < 4; c++)
                    msg[(i0 + r) * HID + h0 + c] = fmaxf(a[r][c], 0.f);
        }
        __syncthreads();
    }

    for (int idx = tid; idx < NA * HID; idx += 512) {
        int a = idx / HID, h = idx - a * HID;
        float s = 0.f;
        #pragma unroll
        for (int j = 0; j < 6; j++) s += msg[ag[a * 6 + j] * HID + h];
        tmp[idx] = s;
    }
    for (int idx = tid; idx < NA * AFD; idx += 512) tmp[NA * HID + idx] = fa[idx];
    __syncthreads();

    for (int task = tid; task < 12 * 50; task += 512) {
        const int a0i = (task / 50) * 4;
        const int h0  = (task % 50) * 4;
        float4 bb = *(const float4*)(W_o_b + h0);
        float a[4][4];
        #pragma unroll
        for (int r = 0; r < 4; r++) { a[r][0]=bb.x; a[r][1]=bb.y; a[r][2]=bb.z; a[r][3]=bb.w; }
        const float* fas = tmp + NA * HID;
        for (int k = 0; k < AFD; k++) {
            float4 w = *(const float4*)(W_o_w + k * HID + h0);
            #pragma unroll
            for (int r = 0; r < 4; r++) {
                float x = fas[(a0i + r) * AFD + k];
                a[r][0] = fmaf(x, w.x, a[r][0]);
                a[r][1] = fmaf(x, w.y, a[r][1]);
                a[r][2] = fmaf(x, w.z, a[r][2]);
                a[r][3] = fmaf(x, w.w, a[r][3]);
            }
        }
        for (int k = 0; k < HID; k++) {
            float4 w = *(const float4*)(W_o_w + (AFD + k) * HID + h0);
            #pragma unroll
            for (int r = 0; r < 4; r++) {
                float x = tmp[(a0i + r) * HID + k];
                a[r][0] = fmaf(x, w.x, a[r][0]);
                a[r][1] = fmaf(x, w.y, a[r][1]);
                a[r][2] = fmaf(x, w.z, a[r][2]);
                a[r][3] = fmaf(x, w.w, a[r][3]);
            }
        }
        #pragma unroll
        for (int r = 0; r < 4; r++)
            #pragma unroll
            for (int c = 0; c < 4; c++)
                binput[(a0i + r) * HID + h0 + c] = fmaxf(a[r][c], 0.f);
    }
    __syncthreads();

    for (int h = tid; h < HID; h += 512) {
        float s = 0.f;
        for (int a = 0; a < NA; a++) s += binput[a * HID + h];
        g_emb[b * HID + h] = s * (1.f / (float)NA);
    }
}

// =====================================================================
// weight prepack: w[Cout][Cin][K] fp32 -> [tile][chunk][ktap][oc128][48] bf16
// =====================================================================
__global__ void wt_prepack_kernel(const float* __restrict__ w,
                                  __nv_bfloat16* __restrict__ wtp,
                                  int Cout, int Cin, int K,
                                  int nchunk, int ntiles)
{
    int idx = blockIdx.x * blockDim.x + threadIdx.x;
    int total = ntiles * nchunk * K * 128 * 48;
    if (idx >= total) return;
    int u48 = idx % 48;
    int oc  = (idx / 48) % 128;
    int kt  = (idx / (48 * 128)) % K;
    int c   = (idx / (48 * 128 * K)) % nchunk;
    int t   =  idx / (48 * 128 * K * nchunk);

    int part = u48 >> 4;
    int cii  = u48 & 15;
    int ci   = c * 16 + cii;
    int ocg  = t * 128 + oc;

    __nv_bfloat16 val = __float2bfloat16(0.f);
    if (ocg < Cout && ci < Cin) {
        float x = w[((size_t)ocg * Cin + ci) * K + kt];
        __nv_bfloat16 hi = __float2bfloat16(x);
        val = (part < 2) ? hi : __float2bfloat16(x - __bfloat162float(hi));
    }
    wtp[idx] = val;
}

// =====================================================================
// input prepack (generic): in[b][ci][l] fp32 -> g_inpack[b][l][chunk][48]
// =====================================================================
__global__ void in_prepack_kernel(const float* __restrict__ in,
                                  int Cin, int nchunk)
{
    int idx = blockIdx.x * blockDim.x + threadIdx.x;
    int total = B_MOL * nchunk * LPROT;
    if (idx >= total) return;
    int l = idx % LPROT;
    int c = (idx / LPROT) % nchunk;
    int b = idx / (LPROT * nchunk);

    unsigned short s[48];
    #pragma unroll
    for (int cii = 0; cii < 16; cii++) {
        int ci = c * 16 + cii;
        float x = (ci < Cin) ? in[((size_t)b * Cin + ci) * LPROT + l] : 0.f;
        __nv_bfloat16 hi = __float2bfloat16(x);
        __nv_bfloat16 lo = __float2bfloat16(x - __bfloat162float(hi));
        unsigned short hb = __bfloat16_as_ushort(hi);
        s[cii]      = hb;
        s[16 + cii] = __bfloat16_as_ushort(lo);
        s[32 + cii] = hb;
    }
    uint4* dst = (uint4*)(g_inpack + ((size_t)(b * LPROT + l) * nchunk + c) * 48);
    const uint4* sv = (const uint4*)s;
    #pragma unroll
    for (int q = 0; q < 6; q++) dst[q] = sv[q];
}

// =====================================================================
// fused embed + prepack for conv0: E[seq[b][l]][ci] -> g_inpack (nchunk=4)
// =====================================================================
__global__ void in_prepack0_kernel(const int* __restrict__ seq,
                                   const float* __restrict__ E)
{
    const int nchunk = 4;
    int idx = blockIdx.x * blockDim.x + threadIdx.x;
    int total = B_MOL * nchunk * LPROT;
    if (idx >= total) return;
    int l = idx % LPROT;
    int c = (idx / LPROT) % nchunk;
    int b = idx / (LPROT * nchunk);

    const float* Erow = E + (size_t)seq[b * LPROT + l] * C0;

    unsigned short s[48];
    #pragma unroll
    for (int cii = 0; cii < 16; cii++) {
        int ci = c * 16 + cii;
        float x = (ci < C0) ? Erow[ci] : 0.f;
        __nv_bfloat16 hi = __float2bfloat16(x);
        __nv_bfloat16 lo = __float2bfloat16(x - __bfloat162float(hi));
        unsigned short hb = __bfloat16_as_ushort(hi);
        s[cii]      = hb;
        s[16 + cii] = __bfloat16_as_ushort(lo);
        s[32 + cii] = hb;
    }
    uint4* dst = (uint4*)(g_inpack + ((size_t)(b * LPROT + l) * nchunk + c) * 48);
    const uint4* sv = (const uint4*)s;
    #pragma unroll
    for (int q = 0; q < 6; q++) dst[q] = sv[q];
}

// =====================================================================
// conv via warp HMMA (m16n8k16 bf16): block = 128 oc x 128 pos, 8 warps.
// =====================================================================
template <int K, int NCHUNK>
__global__ __launch_bounds__(256)
void conv_mma_kernel(const __nv_bfloat16* __restrict__ wtp,
                     const float* __restrict__ bias,
                     float* __restrict__ out, int Cout)
{
    constexpr int PW = 128 + K - 1;
    constexpr int AROWS = K * 128;
    extern __shared__ __nv_bfloat16 smem[];
    __nv_bfloat16* s_a = smem;                  // [K*128][52]
    __nv_bfloat16* s_b = smem + AROWS * 52;     // [PW][52]

    const int tid  = threadIdx.x;
    const int lane = tid & 31;
    const int wid  = tid >> 5;
    const int wm   = wid & 1;
    const int wn   = wid >> 1;
    const int b    = blockIdx.x;
    const int l0   = blockIdx.y * 128;
    const int oc0  = blockIdx.z * 128;
    const int gid  = lane >> 2;
    const int qid  = lane & 3;

    const __nv_bfloat16* wp_tile = wtp + (size_t)blockIdx.z * NCHUNK * AROWS * 48;

    float acc[4][4][4];
    #pragma unroll
    for (int mi = 0; mi < 4; mi++)
        #pragma unroll
        for (int ni = 0; ni < 4; ni++)
            #pragma unroll
            for (int q = 0; q < 4; q++) acc[mi][ni][q] = 0.f;

    for (int c = 0; c < NCHUNK; c++) {
        for (int idx = tid; idx < AROWS * 12; idx += 256) {
            int row = idx / 12, u = idx - row * 12;
            uint2 v = *(const uint2*)(wp_tile + ((size_t)c * AROWS + row) * 48 + u * 4);
            *(uint2*)(s_a + row * 52 + u * 4) = v;
        }
        for (int idx = tid; idx < PW * 12; idx += 256) {
            int p = idx / 12, u = idx - p * 12;
            int l = l0 + p - K / 2;
            uint2 v = make_uint2(0u, 0u);
            if (l >= 0 && l < LPROT)
                v = *(const uint2*)(g_inpack + ((size_t)(b * LPROT + l) * NCHUNK + c) * 48 + u * 4);
            *(uint2*)(s_b + p * 52 + u * 4) = v;
        }
        __syncthreads();

        #pragma unroll 1
        for (int kt = 0; kt < K; kt++) {
            const __nv_bfloat16* sa = s_a + kt * 128 * 52;
            #pragma unroll
            for (int s = 0; s < 3; s++) {
                const int k0 = s * 16 + qid * 2;
                uint32_t afr[4][4];
                #pragma unroll
                for (int mi = 0; mi < 4; mi++) {
                    int r0 = wm * 64 + mi * 16 + gid;
                    afr[mi][0] = *(const uint32_t*)(sa + (r0)     * 52 + k0);
                    afr[mi][1] = *(const uint32_t*)(sa + (r0 + 8) * 52 + k0);
                    afr[mi][2] = *(const uint32_t*)(sa + (r0)     * 52 + k0 + 8);
                    afr[mi][3] = *(const uint32_t*)(sa + (r0 + 8) * 52 + k0 + 8);
                }
                uint32_t bfr[4][2];
                #pragma unroll
                for (int ni = 0; ni < 4; ni++) {
                    int p0 = wn * 32 + ni * 8 + gid + kt;
                    bfr[ni][0] = *(const uint32_t*)(s_b + p0 * 52 + k0);
                    bfr[ni][1] = *(const uint32_t*)(s_b + p0 * 52 + k0 + 8);
                }
                #pragma unroll
                for (int mi = 0; mi < 4; mi++)
                    #pragma unroll
                    for (int ni = 0; ni < 4; ni++)
                        mma16816(acc[mi][ni][0], acc[mi][ni][1], acc[mi][ni][2], acc[mi][ni][3],
                                 afr[mi][0], afr[mi][1], afr[mi][2], afr[mi][3],
                                 bfr[ni][0], bfr[ni][1]);
            }
        }
        __syncthreads();
    }

    #pragma unroll
    for (int mi = 0; mi < 4; mi++) {
        int oc = oc0 + wm * 64 + mi * 16 + gid;
        #pragma unroll
        for (int ni = 0; ni < 4; ni++) {
            int col = l0 + wn * 32 + ni * 8 + qid * 2;
            if (col < LPROT) {
                if (oc < Cout) {
                    float bv = bias[oc];
                    float2 v;
                    v.x = fmaxf(acc[mi][ni][0] + bv, 0.f);
                    v.y = fmaxf(acc[mi][ni][1] + bv, 0.f);
                    *(float2*)(out + ((size_t)b * Cout + oc) * LPROT + col) = v;
                }
                if (oc + 8 < Cout) {
                    float bv = bias[oc + 8];
                    float2 v;
                    v.x = fmaxf(acc[mi][ni][2] + bv, 0.f);
                    v.y = fmaxf(acc[mi][ni][3] + bv, 0.f);
                    *(float2*)(out + ((size_t)b * Cout + oc + 8) * LPROT + col) = v;
                }
            }
        }
    }
}

// =====================================================================
__global__ void maxpool_kernel(const float* __restrict__ in, float* __restrict__ out)
{
    int gwarp = (blockIdx.x * blockDim.x + threadIdx.x) >> 5;
    int lane  = threadIdx.x & 31;
    const int rows = B_MOL * C3;
    if (gwarp >= rows) return;
    const float* p = in + (size_t)gwarp * LPROT;
    float m = -CUDART_INF_F;
    for (int l = lane; l < LPROT; l += 32) m = fmaxf(m, p[l]);
    #pragma unroll
    for (int s = 16; s; s >>= 1) m = fmaxf(m, __shfl_xor_sync(0xFFFFFFFFu, m, s));
    if (lane == 0) out[gwarp] = m;
}

// =====================================================================
__global__ void fc_kernel(const float* __restrict__ emb,
                          const float* __restrict__ prot,
                          const float* __restrict__ w0, const float* __restrict__ b0,
                          const float* __restrict__ w1, const float* __restrict__ b1,
                          const float* __restrict__ w2, const float* __restrict__ b2,
                          float* __restrict__ out)
{
    __shared__ float x[400];
    __shared__ float h1[200];
    __shared__ float h2[100];
    __shared__ float red[256];
    const int b = blockIdx.x;
    const int tid = threadIdx.x;

    for (int i = tid; i < 200; i += 256) {
        x[i]       = emb[b * 200 + i];
        x[200 + i] = prot[b * 200 + i];
    }
    __syncthreads();
    for (int j = tid; j < 200; j += 256) {
        float s = b0[j];
        for (int k = 0; k < 400; k++) s = fmaf(x[k], w0[k * 200 + j], s);
        h1[j] = fmaxf(s, 0.f);
    }
    __syncthreads();
    for (int j = tid; j < 100; j += 256) {
        float s = b1[j];
        for (int k = 0; k < 200; k++) s = fmaf(h1[k], w1[k * 100 + j], s);
        h2[j] = fmaxf(s, 0.f);
    }
    __syncthreads();
    float s = 0.f;
    for (int k = tid; k < 100; k += 256) s = fmaf(h2[k], w2[k], s);
    red[tid] = s;
    __syncthreads();
    for (int st = 128; st; st >>= 1) {
        if (tid < st) red[tid] += red[tid + st];
        __syncthreads();
    }
    if (tid == 0) out[b] = red[0] + b2[0];
}

// =====================================================================
extern "C" void kernel_launch(void* const* d_in, const int* in_sizes, int n_in,
                              void* d_out, int out_size)
{
    const float* fatoms  = (const float*)d_in[0];
    const float* fbonds  = (const float*)d_in[1];
    const int*   agraph  = (const int*)  d_in[2];
    const int*   bgraph  = (const int*)  d_in[3];
    const int*   seq     = (const int*)  d_in[4];
    const float* W_i     = (const float*)d_in[5];
    const float* W_h     = (const float*)d_in[6];
    const float* W_o_w   = (const float*)d_in[7];
    const float* W_o_b   = (const float*)d_in[8];
    const float* embedP  = (const float*)d_in[9];
    const float* c0w     = (const float*)d_in[10];
    const float* c0b     = (const float*)d_in[11];
    const float* c1w     = (const float*)d_in[12];
    const float* c1b     = (const float*)d_in[13];
    const float* c2w     = (const float*)d_in[14];
    const float* c2b     = (const float*)d_in[15];
    const float* fc0w    = (const float*)d_in[16];
    const float* fc0b    = (const float*)d_in[17];
    const float* fc1w    = (const float*)d_in[18];
    const float* fc1b    = (const float*)d_in[19];
    const float* fc2w    = (const float*)d_in[20];
    const float* fc2b    = (const float*)d_in[21];
    float* out = (float*)d_out;

    float *bufA, *bufB, *emb, *prot;
    __nv_bfloat16* wtp;
    cudaGetSymbolAddress((void**)&bufA, g_bufA);
    cudaGetSymbolAddress((void**)&bufB, g_bufB);
    cudaGetSymbolAddress((void**)&emb,  g_emb);
    cudaGetSymbolAddress((void**)&prot, g_prot);
    cudaGetSymbolAddress((void**)&wtp,  g_wtp);

    // lazy one-time stream/event setup (first call is the non-captured
    // correctness run; subsequent captured calls only launch work)
    static cudaStream_t s2 = nullptr;
    static cudaEvent_t evFork = nullptr, evJoin = nullptr;
    if (!s2) {
        cudaStreamCreateWithFlags(&s2, cudaStreamNonBlocking);
        cudaEventCreateWithFlags(&evFork, cudaEventDisableTiming);
        cudaEventCreateWithFlags(&evJoin, cudaEventDisableTiming);
    }

    const int mpnn_smem = 3 * NB * HID * sizeof(float);   // 230400 B
    cudaFuncSetAttribute(mpnn_kernel, cudaFuncAttributeMaxDynamicSharedMemorySize, mpnn_smem);

    const int smem0 = (3 * 128 * 52 + 130 * 52) * 2;
    const int smem1 = (5 * 128 * 52 + 132 * 52) * 2;
    const int smem2 = (7 * 128 * 52 + 134 * 52) * 2;
    cudaFuncSetAttribute((conv_mma_kernel<3, 4>), cudaFuncAttributeMaxDynamicSharedMemorySize, smem0);
    cudaFuncSetAttribute((conv_mma_kernel<5, 6>), cudaFuncAttributeMaxDynamicSharedMemorySize, smem1);
    cudaFuncSetAttribute((conv_mma_kernel<7, 8>), cudaFuncAttributeMaxDynamicSharedMemorySize, smem2);

    // ---- fork: MPNN on side stream ----
    cudaEventRecord(evFork, 0);
    cudaStreamWaitEvent(s2, evFork, 0);
    mpnn_kernel<<<B_MOL, 512, mpnn_smem, s2>>>(fatoms, fbonds, agraph, bgraph,
                                               W_i, W_h, W_o_w, W_o_b);
    cudaEventRecord(evJoin, s2);

    // ---- protein tower on main stream ----
    // weight prepacks (input-only deps, separate regions)
    {
        int w0t = 1 * 4 * 3 * 128 * 48;
        wt_prepack_kernel<<<(w0t + 255) / 256, 256>>>(c0w, wtp + WT0_OFF, C1, C0, 3, 4, 1);
        int w1t = 1 * 6 * 5 * 128 * 48;
        wt_prepack_kernel<<<(w1t + 255) / 256, 256>>>(c1w, wtp + WT1_OFF, C2, C1, 5, 6, 1);
        int w2t = 2 * 8 * 7 * 128 * 48;
        wt_prepack_kernel<<<(w2t + 255) / 256, 256>>>(c2w, wtp + WT2_OFF, C3, C2, 7, 8, 2);
    }
    // conv0 input: fused embed+prepack
    {
        int itot = B_MOL * 4 * LPROT;
        in_prepack0_kernel<<<(itot + 255) / 256, 256>>>(seq, embedP);
        dim3 g(B_MOL, 8, 1);
        conv_mma_kernel<3, 4><<<g, 256, smem0>>>(wtp + WT0_OFF, c0b, bufB, C1);
    }
    {
        int itot = B_MOL * 6 * LPROT;
        in_prepack_kernel<<<(itot + 255) / 256, 256>>>(bufB, C1, 6);
        dim3 g(B_MOL, 8, 1);
        conv_mma_kernel<5, 6><<<g, 256, smem1>>>(wtp + WT1_OFF, c1b, bufA, C2);
    }
    {
        int itot = B_MOL * 8 * LPROT;
        in_prepack_kernel<<<(itot + 255) / 256, 256>>>(bufA, C2, 8);
        dim3 g(B_MOL, 8, 2);
        conv_mma_kernel<7, 8><<<g, 256, smem2>>>(wtp + WT2_OFF, c2b, bufB, C3);
    }
    {
        int rows = B_MOL * C3;
        maxpool_kernel<<<(rows + 7) / 8, 256>>>(bufB, prot);
    }

    // ---- join: fc needs both branches ----
    cudaStreamWaitEvent(0, evJoin, 0);
    fc_kernel<<<B_MOL, 256>>>(emb, prot, fc0w, fc0b, fc1w, fc1b, fc2w, fc2b, out);
}